// round 14
// baseline (speedup 1.0000x reference)
#include <cuda_runtime.h>
#include <cuda_bf16.h>
#include <math_constants.h>
#include <cstdint>

#define B   4
#define CD  512
#define HW  4096
#define LOG2E 1.4426950408889634f

#define ATQ 128                // queries per attnA block
#define ATN 256                // keys per n-tile
#define NCHUNK ((HW / ATN) * 8)   // 16 n-tiles * 8 c-chunks = 128
// stage layout (bytes): Qh 0, Ql 16384, Kh 32768, Kl 65536; stage = 98304
#define STG 98304
#define SMEM_DYN (2 * STG)     // 196608
#define CAP 256                // per-row candidate list capacity

// -------- scratch (device globals; no allocations) --------
__device__ __nv_bfloat16 g_Qh[(size_t)B * HW * CD];
__device__ __nv_bfloat16 g_Ql[(size_t)B * HW * CD];
__device__ __nv_bfloat16 g_Kh[(size_t)B * HW * CD];
__device__ __nv_bfloat16 g_Kl[(size_t)B * HW * CD];
__device__ float g_Vt[(size_t)B * HW * CD];    // (b, k, v)
__device__ float g_L [(size_t)B * HW * HW];    // logits (log2 scale), (b, q, k)
__device__ float g_M [(size_t)B * HW * CD];
__device__ float g_S [(size_t)B * HW * CD];
__device__ float g_mean[3 * B * CD];           // aid: 0=c_1x, 1=s_1x, 2=c_x
__device__ float g_rstd[3 * B * CD];

// ---------------- ptx helpers ----------------
__device__ __forceinline__ uint32_t s_u32(const void* p) {
    return (uint32_t)__cvta_generic_to_shared(p);
}
__device__ __forceinline__ void cp16(uint32_t s, const void* g) {
    asm volatile("cp.async.cg.shared.global [%0], [%1], 16;" :: "r"(s), "l"(g));
}
__device__ __forceinline__ void cp_commit() { asm volatile("cp.async.commit_group;"); }
__device__ __forceinline__ void cp_wait0()  { asm volatile("cp.async.wait_group 0;"); }
__device__ __forceinline__ void cp_wait1()  { asm volatile("cp.async.wait_group 1;"); }

__device__ __forceinline__ void ldm4(uint32_t* r, uint32_t addr) {
    asm volatile("ldmatrix.sync.aligned.m8n8.x4.shared.b16 {%0,%1,%2,%3}, [%4];"
                 : "=r"(r[0]), "=r"(r[1]), "=r"(r[2]), "=r"(r[3]) : "r"(addr));
}
__device__ __forceinline__ void mma_bf16(float* c, const uint32_t* a, uint32_t b0, uint32_t b1) {
    asm volatile(
        "mma.sync.aligned.m16n8k16.row.col.f32.bf16.bf16.f32 "
        "{%0,%1,%2,%3}, {%4,%5,%6,%7}, {%8,%9}, {%0,%1,%2,%3};"
        : "+f"(c[0]), "+f"(c[1]), "+f"(c[2]), "+f"(c[3])
        : "r"(a[0]), "r"(a[1]), "r"(a[2]), "r"(a[3]), "r"(b0), "r"(b1));
}

// ============================================================
// Kernel 1: instance-norm stats for all three inputs
// ============================================================
__global__ void stats_kernel(const float* __restrict__ c_x,
                             const float* __restrict__ c_1x,
                             const float* __restrict__ s_1x) {
    int aid = blockIdx.y;
    int bc  = blockIdx.x;
    const float* src  = (aid == 0) ? c_1x : (aid == 1) ? s_1x : c_x;
    const float* base = src + (size_t)bc * HW;
    int t = threadIdx.x;

    float sum = 0.f, ss = 0.f;
#pragma unroll
    for (int i = 0; i < 16; i++) {
        float v = base[t + i * 256];
        sum += v;
        ss = fmaf(v, v, ss);
    }
    __shared__ float red0[8], red1[8];
#pragma unroll
    for (int o = 16; o; o >>= 1) {
        sum += __shfl_xor_sync(0xffffffffu, sum, o);
        ss  += __shfl_xor_sync(0xffffffffu, ss,  o);
    }
    if ((t & 31) == 0) { red0[t >> 5] = sum; red1[t >> 5] = ss; }
    __syncthreads();
    if (t == 0) {
        float s1 = 0.f, s2 = 0.f;
#pragma unroll
        for (int i = 0; i < 8; i++) { s1 += red0[i]; s2 += red1[i]; }
        float mean = s1 * (1.f / HW);
        float var  = s2 * (1.f / HW) - mean * mean;
        g_mean[aid * B * CD + bc] = mean;
        g_rstd[aid * B * CD + bc] = rsqrtf(var + 1e-5f);
    }
}

// ============================================================
// Kernel 2: normalize + transpose + bf16 hi/lo split
// ============================================================
__global__ void convert_kernel(const float* __restrict__ c_1x,
                               const float* __restrict__ s_1x) {
    __shared__ float tile[32][33];
    int which = blockIdx.z >> 2;
    int b     = blockIdx.z & 3;
    const float* src = which ? s_1x : c_1x;
    __nv_bfloat16* dh = which ? g_Kh : g_Qh;
    __nv_bfloat16* dl = which ? g_Kl : g_Ql;
    float scale = which ? 1.f : LOG2E;
    int s0 = blockIdx.x * 32, c0 = blockIdx.y * 32;
    int tx = threadIdx.x, ty = threadIdx.y;
#pragma unroll
    for (int i = 0; i < 4; i++) {
        int c = c0 + ty + i * 8;
        float mean = g_mean[which * B * CD + b * CD + c];
        float rs   = g_rstd[which * B * CD + b * CD + c] * scale;
        float v = src[((size_t)b * CD + c) * HW + s0 + tx];
        tile[ty + i * 8][tx] = (v - mean) * rs;
    }
    __syncthreads();
#pragma unroll
    for (int i = 0; i < 4; i++) {
        int s = s0 + ty + i * 8;
        float x = tile[tx][ty + i * 8];
        __nv_bfloat16 hi = __float2bfloat16(x);
        __nv_bfloat16 lo = __float2bfloat16(x - __bfloat162float(hi));
        size_t off = ((size_t)b * HW + s) * CD + c0 + tx;
        dh[off] = hi;
        dl[off] = lo;
    }
}

// ============================================================
// Kernel 3: transpose s_x (b, v, k) -> Vt (b, k, v)
// ============================================================
__global__ void vtrans_kernel(const float* __restrict__ s_x) {
    __shared__ float tile[32][33];
    int b  = blockIdx.z;
    int k0 = blockIdx.x * 32;
    int v0 = blockIdx.y * 32;
    int tx = threadIdx.x, ty = threadIdx.y;
    const float* src = s_x + (size_t)b * CD * HW;
#pragma unroll
    for (int i = 0; i < 4; i++)
        tile[ty + i * 8][tx] = src[(size_t)(v0 + ty + i * 8) * HW + k0 + tx];
    __syncthreads();
    float* dst = g_Vt + (size_t)b * HW * CD;
#pragma unroll
    for (int i = 0; i < 4; i++)
        dst[(size_t)(k0 + ty + i * 8) * CD + v0 + tx] = tile[tx][ty + i * 8];
}

// ============================================================
// Kernel 4 (attn): bf16 3-split QK^T via mma.sync + FUSED
// softmax/V-gather tail (logits L2-hot).
//   grid (HW/128, B) = 128 blocks (single wave), 256 threads,
//   8 warps (2m x 4n), warp tile 64x64, n-tile 256, c-chunk 64.
// ============================================================
__global__ __launch_bounds__(256, 1) void attn_kernel() {
    extern __shared__ char dsm[];
    __shared__ float rms[4][128];
    __shared__ float s_rm[128];
    __shared__ int   s_cnt[8];
    uint32_t sb = s_u32(dsm);

    int b  = blockIdx.y;
    int q0 = blockIdx.x * ATQ;
    int t  = threadIdx.x;
    int wid = t >> 5, lane = t & 31;
    int mw = wid >> 2, nw = wid & 3;       // 2 m-groups(64) x 4 n-groups(64)

    const __nv_bfloat16* Qhg = g_Qh + ((size_t)b * HW + q0) * CD;
    const __nv_bfloat16* Qlg = g_Ql + ((size_t)b * HW + q0) * CD;
    const __nv_bfloat16* Khg = g_Kh + (size_t)b * HW * CD;
    const __nv_bfloat16* Klg = g_Kl + (size_t)b * HW * CD;
    float* Lb = g_L + ((size_t)b * HW + q0) * HW;

    auto fill = [&](int g) {
        uint32_t st = sb + (uint32_t)(g & 1) * STG;
        int c0 = (g & 7) * 64;
        int k0 = (g >> 3) * ATN;
#pragma unroll
        for (int r = 0; r < 4; r++) {
            int i = t + r * 256;
            int row = i >> 3, c16 = i & 7;
            uint32_t so = (uint32_t)(row * 128 + ((c16 ^ (row & 7)) << 4));
            size_t gi = (size_t)row * CD + c0 + c16 * 8;
            cp16(st + so,         Qhg + gi);
            cp16(st + 16384 + so, Qlg + gi);
        }
#pragma unroll
        for (int r = 0; r < 8; r++) {
            int i = t + r * 256;
            int key = i >> 3, c16 = i & 7;
            uint32_t so = (uint32_t)(key * 128 + ((c16 ^ (key & 7)) << 4));
            size_t gi = (size_t)(k0 + key) * CD + c0 + c16 * 8;
            cp16(st + 32768 + so, Khg + gi);
            cp16(st + 65536 + so, Klg + gi);
        }
    };

    fill(0); cp_commit();

    float acc[4][8][4];
#pragma unroll
    for (int mb = 0; mb < 4; mb++)
#pragma unroll
        for (int nb = 0; nb < 8; nb++)
#pragma unroll
            for (int i = 0; i < 4; i++) acc[mb][nb][i] = 0.f;
    float rmx[4][2];
#pragma unroll
    for (int mb = 0; mb < 4; mb++) { rmx[mb][0] = -CUDART_INF_F; rmx[mb][1] = -CUDART_INF_F; }

    int tr  = lane & 15, th = lane >> 4;        // A ldmatrix mapping
    int trb = lane & 7,  tq = lane >> 3;        // B ldmatrix mapping

    for (int g = 0; g < NCHUNK; g++) {
        __syncthreads();
        if (g + 1 < NCHUNK) { fill(g + 1); cp_commit(); cp_wait1(); }
        else                { cp_wait0(); }
        __syncthreads();

        uint32_t st = sb + (uint32_t)(g & 1) * STG;

#pragma unroll
        for (int ks = 0; ks < 4; ks++) {
            uint32_t aQh[4][4], aQl[4][4], bKh[4][4], bKl[4][4];
#pragma unroll
            for (int mb = 0; mb < 4; mb++) {
                int row = mw * 64 + mb * 16 + tr;
                int c16 = ks * 2 + th;
                uint32_t so = (uint32_t)(row * 128 + ((c16 ^ (row & 7)) << 4));
                ldm4(aQh[mb], st + so);
                ldm4(aQl[mb], st + 16384u + so);
            }
#pragma unroll
            for (int pr = 0; pr < 4; pr++) {
                int key = nw * 64 + pr * 16 + (tq >> 1) * 8 + trb;
                int c16 = ks * 2 + (tq & 1);
                uint32_t so = (uint32_t)(key * 128 + ((c16 ^ (key & 7)) << 4));
                ldm4(bKh[pr], st + 32768u + so);
                ldm4(bKl[pr], st + 65536u + so);
            }
#pragma unroll
            for (int mb = 0; mb < 4; mb++)
#pragma unroll
                for (int nb = 0; nb < 8; nb++)
                    mma_bf16(acc[mb][nb], aQh[mb],
                             bKh[nb >> 1][(nb & 1) * 2], bKh[nb >> 1][(nb & 1) * 2 + 1]);
#pragma unroll
            for (int mb = 0; mb < 4; mb++)
#pragma unroll
                for (int nb = 0; nb < 8; nb++)
                    mma_bf16(acc[mb][nb], aQh[mb],
                             bKl[nb >> 1][(nb & 1) * 2], bKl[nb >> 1][(nb & 1) * 2 + 1]);
#pragma unroll
            for (int mb = 0; mb < 4; mb++)
#pragma unroll
                for (int nb = 0; nb < 8; nb++)
                    mma_bf16(acc[mb][nb], aQl[mb],
                             bKh[nb >> 1][(nb & 1) * 2], bKh[nb >> 1][(nb & 1) * 2 + 1]);
        }

        if ((g & 7) == 7) {
            int nt = g >> 3;
            int colb = nt * ATN + nw * 64 + (lane & 3) * 2;
#pragma unroll
            for (int mb = 0; mb < 4; mb++) {
                int r0 = mw * 64 + mb * 16 + (lane >> 2);
#pragma unroll
                for (int nb = 0; nb < 8; nb++) {
                    float* a4 = acc[mb][nb];
                    rmx[mb][0] = fmaxf(rmx[mb][0], fmaxf(a4[0], a4[1]));
                    rmx[mb][1] = fmaxf(rmx[mb][1], fmaxf(a4[2], a4[3]));
                    *(float2*)(Lb + (size_t)r0 * HW + colb + nb * 8)       = make_float2(a4[0], a4[1]);
                    *(float2*)(Lb + (size_t)(r0 + 8) * HW + colb + nb * 8) = make_float2(a4[2], a4[3]);
#pragma unroll
                    for (int i = 0; i < 4; i++) a4[i] = 0.f;
                }
            }
        }
    }

    // --- rowmax reduce into smem ---
#pragma unroll
    for (int mb = 0; mb < 4; mb++)
#pragma unroll
        for (int h = 0; h < 2; h++) {
            float v = rmx[mb][h];
            v = fmaxf(v, __shfl_xor_sync(0xffffffffu, v, 1));
            v = fmaxf(v, __shfl_xor_sync(0xffffffffu, v, 2));
            rmx[mb][h] = v;
        }
    if ((lane & 3) == 0) {
#pragma unroll
        for (int mb = 0; mb < 4; mb++)
#pragma unroll
            for (int h = 0; h < 2; h++)
                rms[nw][mw * 64 + mb * 16 + (lane >> 2) + h * 8] = rmx[mb][h];
    }
    __syncthreads();
    if (t < 128)
        s_rm[t] = fmaxf(fmaxf(rms[0][t], rms[1][t]), fmaxf(rms[2][t], rms[3][t]));
    __syncthreads();

    // ===== FUSED TAIL: softmax scan + sparse V gather (logits L2-hot) =====
    // per-warp candidate lists aliased onto pipeline smem (dead now)
    int*   keyL = (int*)dsm           + wid * CAP;
    float* pL   = (float*)(dsm + 16384) + wid * CAP;
    const float* Vg = g_Vt + (size_t)b * HW * CD;

    for (int rr = 0; rr < 16; rr++) {
        int row = wid * 16 + rr;
        int q   = q0 + row;
        float m   = s_rm[row];
        float thr = m - 34.0f;                   // 2^-34 ~ 6e-11
        const float4* Lr = (const float4*)(Lb + (size_t)row * HW);

        if (lane == 0) s_cnt[wid] = 0;
        __syncwarp();

        float psum = 0.f;
#pragma unroll 4
        for (int i = 0; i < 32; i++) {
            int k4 = i * 32 + lane;
            float4 l4 = Lr[k4];
            float mx = fmaxf(fmaxf(l4.x, l4.y), fmaxf(l4.z, l4.w));
            if (mx > thr) {
#pragma unroll
                for (int jj = 0; jj < 4; jj++) {
                    float lv = (&l4.x)[jj];
                    if (lv > thr) {
                        float p;
                        asm("ex2.approx.f32 %0, %1;" : "=f"(p) : "f"(lv - m));
                        psum += p;
                        int idx = atomicAdd(&s_cnt[wid], 1);
                        if (idx < CAP) { keyL[idx] = k4 * 4 + jj; pL[idx] = p; }
                    }
                }
            }
        }
#pragma unroll
        for (int o = 16; o; o >>= 1)
            psum += __shfl_xor_sync(0xffffffffu, psum, o);
        __syncwarp();

        int n = min(s_cnt[wid], CAP);
        float accM[16], accM2[16];
#pragma unroll
        for (int i = 0; i < 16; i++) { accM[i] = 0.f; accM2[i] = 0.f; }

        for (int i = 0; i < n; i++) {
            int   k = keyL[i];
            float p = pL[i];
            const float4* vr = (const float4*)(Vg + (size_t)k * CD) + lane;
#pragma unroll
            for (int j = 0; j < 4; j++) {
                float4 v = vr[j << 5];
                float a0 = p * v.x, a1 = p * v.y, a2 = p * v.z, a3 = p * v.w;
                accM[4*j]   += a0; accM2[4*j]   = fmaf(a0, v.x, accM2[4*j]);
                accM[4*j+1] += a1; accM2[4*j+1] = fmaf(a1, v.y, accM2[4*j+1]);
                accM[4*j+2] += a2; accM2[4*j+2] = fmaf(a2, v.z, accM2[4*j+2]);
                accM[4*j+3] += a3; accM2[4*j+3] = fmaf(a3, v.w, accM2[4*j+3]);
            }
        }

        float inv = 1.f / psum;
        float* Mo = g_M + ((size_t)b * HW + q) * CD;
        float* So = g_S + ((size_t)b * HW + q) * CD;
#pragma unroll
        for (int j = 0; j < 4; j++) {
            float4 mv, sv;
            float mm, e2, var;
            mm = accM[4*j] * inv;   e2 = accM2[4*j] * inv;   var = e2 - mm * mm;
            mv.x = mm; sv.x = sqrtf(fmaxf(var, 1e-6f));
            mm = accM[4*j+1] * inv; e2 = accM2[4*j+1] * inv; var = e2 - mm * mm;
            mv.y = mm; sv.y = sqrtf(fmaxf(var, 1e-6f));
            mm = accM[4*j+2] * inv; e2 = accM2[4*j+2] * inv; var = e2 - mm * mm;
            mv.z = mm; sv.z = sqrtf(fmaxf(var, 1e-6f));
            mm = accM[4*j+3] * inv; e2 = accM2[4*j+3] * inv; var = e2 - mm * mm;
            mv.w = mm; sv.w = sqrtf(fmaxf(var, 1e-6f));
            int v = j * 128 + lane * 4;
            *(float4*)(Mo + v) = mv;
            *(float4*)(So + v) = sv;
        }
        __syncwarp();
    }
}

// ============================================================
// Kernel 5: out[b][v][s] = S[b][s][v] * IN(c_x)[b][v][s] + M[b][s][v]
// ============================================================
__global__ void epilogue_kernel(const float* __restrict__ c_x,
                                float* __restrict__ out) {
    __shared__ float tm[32][33], ts[32][33];
    int b  = blockIdx.z;
    int s0 = blockIdx.x * 32;
    int v0 = blockIdx.y * 32;
    int tx = threadIdx.x, ty = threadIdx.y;
    const float* Mb = g_M + (size_t)b * HW * CD;
    const float* Sb = g_S + (size_t)b * HW * CD;
#pragma unroll
    for (int i = 0; i < 4; i++) {
        int s = s0 + ty + i * 8;
        tm[ty + i * 8][tx] = Mb[(size_t)s * CD + v0 + tx];
        ts[ty + i * 8][tx] = Sb[(size_t)s * CD + v0 + tx];
    }
    __syncthreads();
#pragma unroll
    for (int i = 0; i < 4; i++) {
        int v = v0 + ty + i * 8;
        float mean = g_mean[2 * B * CD + b * CD + v];
        float rstd = g_rstd[2 * B * CD + b * CD + v];
        size_t off = ((size_t)b * CD + v) * HW + s0 + tx;
        float cn = (c_x[off] - mean) * rstd;
        out[off] = ts[tx][ty + i * 8] * cn + tm[tx][ty + i * 8];
    }
}

// ============================================================
extern "C" void kernel_launch(void* const* d_in, const int* in_sizes, int n_in,
                              void* d_out, int out_size) {
    const float* c_x  = (const float*)d_in[0];
    const float* s_x  = (const float*)d_in[1];
    const float* c_1x = (const float*)d_in[2];
    const float* s_1x = (const float*)d_in[3];
    float* out = (float*)d_out;

    stats_kernel<<<dim3(B * CD, 3), 256>>>(c_x, c_1x, s_1x);
    convert_kernel<<<dim3(HW / 32, CD / 32, 2 * B), dim3(32, 8)>>>(c_1x, s_1x);
    vtrans_kernel<<<dim3(HW / 32, CD / 32, B), dim3(32, 8)>>>(s_x);

    cudaFuncSetAttribute(attn_kernel, cudaFuncAttributeMaxDynamicSharedMemorySize, SMEM_DYN);
    attn_kernel<<<dim3(HW / ATQ, B), 256, SMEM_DYN>>>();

    epilogue_kernel<<<dim3(HW / 32, CD / 32, B), dim3(32, 8)>>>(c_x, out);
}

// round 15
// speedup vs baseline: 1.4001x; 1.4001x over previous
#include <cuda_runtime.h>
#include <cuda_bf16.h>
#include <math_constants.h>
#include <cstdint>

#define B   4
#define CD  512
#define HW  4096
#define LOG2E 1.4426950408889634f

#define ATQ 128                // queries per attnA block
#define ATN 256                // keys per n-tile
#define NCHUNK ((HW / ATN) * 8)   // 16 n-tiles * 8 c-chunks = 128
// stage layout (bytes): Qh 0, Ql 16384, Kh 32768, Kl 65536; stage = 98304
#define STG 98304
#define SMEM_DYN (2 * STG)     // 196608
#define CAP 256                // per-row candidate list capacity
#define MS_STRIDE 516          // padded row stride (floats) for smem M/S
// attnBC smem: keyL 32K, pL 32K, sM 66048, sS 66048
#define BC_SMEM (65536 + 2 * 32 * MS_STRIDE * 4)

// -------- scratch (device globals; no allocations) --------
__device__ __nv_bfloat16 g_Qh[(size_t)B * HW * CD];
__device__ __nv_bfloat16 g_Ql[(size_t)B * HW * CD];
__device__ __nv_bfloat16 g_Kh[(size_t)B * HW * CD];
__device__ __nv_bfloat16 g_Kl[(size_t)B * HW * CD];
__device__ float g_Vt[(size_t)B * HW * CD];    // (b, k, v)
__device__ float g_L [(size_t)B * HW * HW];    // logits (log2 scale), (b, q, k)
__device__ float g_rowmax[B * HW];
__device__ float g_mean[3 * B * CD];           // aid: 0=c_1x, 1=s_1x, 2=c_x
__device__ float g_rstd[3 * B * CD];

// ---------------- ptx helpers ----------------
__device__ __forceinline__ uint32_t s_u32(const void* p) {
    return (uint32_t)__cvta_generic_to_shared(p);
}
__device__ __forceinline__ void cp16(uint32_t s, const void* g) {
    asm volatile("cp.async.cg.shared.global [%0], [%1], 16;" :: "r"(s), "l"(g));
}
__device__ __forceinline__ void cp_commit() { asm volatile("cp.async.commit_group;"); }
__device__ __forceinline__ void cp_wait0()  { asm volatile("cp.async.wait_group 0;"); }
__device__ __forceinline__ void cp_wait1()  { asm volatile("cp.async.wait_group 1;"); }

__device__ __forceinline__ void ldm4(uint32_t* r, uint32_t addr) {
    asm volatile("ldmatrix.sync.aligned.m8n8.x4.shared.b16 {%0,%1,%2,%3}, [%4];"
                 : "=r"(r[0]), "=r"(r[1]), "=r"(r[2]), "=r"(r[3]) : "r"(addr));
}
__device__ __forceinline__ void mma_bf16(float* c, const uint32_t* a, uint32_t b0, uint32_t b1) {
    asm volatile(
        "mma.sync.aligned.m16n8k16.row.col.f32.bf16.bf16.f32 "
        "{%0,%1,%2,%3}, {%4,%5,%6,%7}, {%8,%9}, {%0,%1,%2,%3};"
        : "+f"(c[0]), "+f"(c[1]), "+f"(c[2]), "+f"(c[3])
        : "r"(a[0]), "r"(a[1]), "r"(a[2]), "r"(a[3]), "r"(b0), "r"(b1));
}

// ============================================================
// Kernel 1: instance-norm stats for all three inputs
// ============================================================
__global__ void stats_kernel(const float* __restrict__ c_x,
                             const float* __restrict__ c_1x,
                             const float* __restrict__ s_1x) {
    int aid = blockIdx.y;
    int bc  = blockIdx.x;
    const float* src  = (aid == 0) ? c_1x : (aid == 1) ? s_1x : c_x;
    const float* base = src + (size_t)bc * HW;
    int t = threadIdx.x;

    float sum = 0.f, ss = 0.f;
#pragma unroll
    for (int i = 0; i < 16; i++) {
        float v = base[t + i * 256];
        sum += v;
        ss = fmaf(v, v, ss);
    }
    __shared__ float red0[8], red1[8];
#pragma unroll
    for (int o = 16; o; o >>= 1) {
        sum += __shfl_xor_sync(0xffffffffu, sum, o);
        ss  += __shfl_xor_sync(0xffffffffu, ss,  o);
    }
    if ((t & 31) == 0) { red0[t >> 5] = sum; red1[t >> 5] = ss; }
    __syncthreads();
    if (t == 0) {
        float s1 = 0.f, s2 = 0.f;
#pragma unroll
        for (int i = 0; i < 8; i++) { s1 += red0[i]; s2 += red1[i]; }
        float mean = s1 * (1.f / HW);
        float var  = s2 * (1.f / HW) - mean * mean;
        g_mean[aid * B * CD + bc] = mean;
        g_rstd[aid * B * CD + bc] = rsqrtf(var + 1e-5f);
    }
}

// ============================================================
// Kernel 2 (fused prep): z 0..7 = normalize+transpose+split
//   (which = z>>2, b = z&3); z 8..11 = vtrans for b = z-8.
// ============================================================
__global__ void prep_kernel(const float* __restrict__ c_1x,
                            const float* __restrict__ s_1x,
                            const float* __restrict__ s_x) {
    __shared__ float tile[32][33];
    int z  = blockIdx.z;
    int tx = threadIdx.x, ty = threadIdx.y;

    if (z < 8) {
        int which = z >> 2;
        int b     = z & 3;
        const float* src = which ? s_1x : c_1x;
        __nv_bfloat16* dh = which ? g_Kh : g_Qh;
        __nv_bfloat16* dl = which ? g_Kl : g_Ql;
        float scale = which ? 1.f : LOG2E;
        int s0 = blockIdx.x * 32, c0 = blockIdx.y * 32;
#pragma unroll
        for (int i = 0; i < 4; i++) {
            int c = c0 + ty + i * 8;
            float mean = g_mean[which * B * CD + b * CD + c];
            float rs   = g_rstd[which * B * CD + b * CD + c] * scale;
            float v = src[((size_t)b * CD + c) * HW + s0 + tx];
            tile[ty + i * 8][tx] = (v - mean) * rs;
        }
        __syncthreads();
#pragma unroll
        for (int i = 0; i < 4; i++) {
            int s = s0 + ty + i * 8;
            float x = tile[tx][ty + i * 8];
            __nv_bfloat16 hi = __float2bfloat16(x);
            __nv_bfloat16 lo = __float2bfloat16(x - __bfloat162float(hi));
            size_t off = ((size_t)b * HW + s) * CD + c0 + tx;
            dh[off] = hi;
            dl[off] = lo;
        }
    } else {
        int b  = z - 8;
        int k0 = blockIdx.x * 32;
        int v0 = blockIdx.y * 32;
        const float* src = s_x + (size_t)b * CD * HW;
#pragma unroll
        for (int i = 0; i < 4; i++)
            tile[ty + i * 8][tx] = src[(size_t)(v0 + ty + i * 8) * HW + k0 + tx];
        __syncthreads();
        float* dst = g_Vt + (size_t)b * HW * CD;
#pragma unroll
        for (int i = 0; i < 4; i++)
            dst[(size_t)(k0 + ty + i * 8) * CD + v0 + tx] = tile[tx][ty + i * 8];
    }
}

// ============================================================
// Kernel 3 (attnA): bf16 3-split QK^T via mma.sync, logits + rowmax
//   grid (HW/128, B) = 128 blocks (single wave), 256 threads,
//   8 warps (2m x 4n), warp tile 64x64, n-tile 256, c-chunk 64.
//   (R11/R13 config — best measured.)
// ============================================================
__global__ __launch_bounds__(256, 1) void attnA_kernel() {
    extern __shared__ char dsm[];
    __shared__ float rms[4][128];
    uint32_t sb = s_u32(dsm);

    int b  = blockIdx.y;
    int q0 = blockIdx.x * ATQ;
    int t  = threadIdx.x;
    int wid = t >> 5, lane = t & 31;
    int mw = wid >> 2, nw = wid & 3;       // 2 m-groups(64) x 4 n-groups(64)

    const __nv_bfloat16* Qhg = g_Qh + ((size_t)b * HW + q0) * CD;
    const __nv_bfloat16* Qlg = g_Ql + ((size_t)b * HW + q0) * CD;
    const __nv_bfloat16* Khg = g_Kh + (size_t)b * HW * CD;
    const __nv_bfloat16* Klg = g_Kl + (size_t)b * HW * CD;
    float* Lb = g_L + ((size_t)b * HW + q0) * HW;

    auto fill = [&](int g) {
        uint32_t st = sb + (uint32_t)(g & 1) * STG;
        int c0 = (g & 7) * 64;
        int k0 = (g >> 3) * ATN;
#pragma unroll
        for (int r = 0; r < 4; r++) {
            int i = t + r * 256;
            int row = i >> 3, c16 = i & 7;
            uint32_t so = (uint32_t)(row * 128 + ((c16 ^ (row & 7)) << 4));
            size_t gi = (size_t)row * CD + c0 + c16 * 8;
            cp16(st + so,         Qhg + gi);
            cp16(st + 16384 + so, Qlg + gi);
        }
#pragma unroll
        for (int r = 0; r < 8; r++) {
            int i = t + r * 256;
            int key = i >> 3, c16 = i & 7;
            uint32_t so = (uint32_t)(key * 128 + ((c16 ^ (key & 7)) << 4));
            size_t gi = (size_t)(k0 + key) * CD + c0 + c16 * 8;
            cp16(st + 32768 + so, Khg + gi);
            cp16(st + 65536 + so, Klg + gi);
        }
    };

    fill(0); cp_commit();

    float acc[4][8][4];
#pragma unroll
    for (int mb = 0; mb < 4; mb++)
#pragma unroll
        for (int nb = 0; nb < 8; nb++)
#pragma unroll
            for (int i = 0; i < 4; i++) acc[mb][nb][i] = 0.f;
    float rmx[4][2];
#pragma unroll
    for (int mb = 0; mb < 4; mb++) { rmx[mb][0] = -CUDART_INF_F; rmx[mb][1] = -CUDART_INF_F; }

    int tr  = lane & 15, th = lane >> 4;        // A ldmatrix mapping
    int trb = lane & 7,  tq = lane >> 3;        // B ldmatrix mapping

    for (int g = 0; g < NCHUNK; g++) {
        __syncthreads();
        if (g + 1 < NCHUNK) { fill(g + 1); cp_commit(); cp_wait1(); }
        else                { cp_wait0(); }
        __syncthreads();

        uint32_t st = sb + (uint32_t)(g & 1) * STG;

#pragma unroll
        for (int ks = 0; ks < 4; ks++) {
            uint32_t aQh[4][4], aQl[4][4], bKh[4][4], bKl[4][4];
#pragma unroll
            for (int mb = 0; mb < 4; mb++) {
                int row = mw * 64 + mb * 16 + tr;
                int c16 = ks * 2 + th;
                uint32_t so = (uint32_t)(row * 128 + ((c16 ^ (row & 7)) << 4));
                ldm4(aQh[mb], st + so);
                ldm4(aQl[mb], st + 16384u + so);
            }
#pragma unroll
            for (int pr = 0; pr < 4; pr++) {
                int key = nw * 64 + pr * 16 + (tq >> 1) * 8 + trb;
                int c16 = ks * 2 + (tq & 1);
                uint32_t so = (uint32_t)(key * 128 + ((c16 ^ (key & 7)) << 4));
                ldm4(bKh[pr], st + 32768u + so);
                ldm4(bKl[pr], st + 65536u + so);
            }
#pragma unroll
            for (int mb = 0; mb < 4; mb++)
#pragma unroll
                for (int nb = 0; nb < 8; nb++)
                    mma_bf16(acc[mb][nb], aQh[mb],
                             bKh[nb >> 1][(nb & 1) * 2], bKh[nb >> 1][(nb & 1) * 2 + 1]);
#pragma unroll
            for (int mb = 0; mb < 4; mb++)
#pragma unroll
                for (int nb = 0; nb < 8; nb++)
                    mma_bf16(acc[mb][nb], aQh[mb],
                             bKl[nb >> 1][(nb & 1) * 2], bKl[nb >> 1][(nb & 1) * 2 + 1]);
#pragma unroll
            for (int mb = 0; mb < 4; mb++)
#pragma unroll
                for (int nb = 0; nb < 8; nb++)
                    mma_bf16(acc[mb][nb], aQl[mb],
                             bKh[nb >> 1][(nb & 1) * 2], bKh[nb >> 1][(nb & 1) * 2 + 1]);
        }

        if ((g & 7) == 7) {
            int nt = g >> 3;
            int colb = nt * ATN + nw * 64 + (lane & 3) * 2;
#pragma unroll
            for (int mb = 0; mb < 4; mb++) {
                int r0 = mw * 64 + mb * 16 + (lane >> 2);
#pragma unroll
                for (int nb = 0; nb < 8; nb++) {
                    float* a4 = acc[mb][nb];
                    rmx[mb][0] = fmaxf(rmx[mb][0], fmaxf(a4[0], a4[1]));
                    rmx[mb][1] = fmaxf(rmx[mb][1], fmaxf(a4[2], a4[3]));
                    *(float2*)(Lb + (size_t)r0 * HW + colb + nb * 8)       = make_float2(a4[0], a4[1]);
                    *(float2*)(Lb + (size_t)(r0 + 8) * HW + colb + nb * 8) = make_float2(a4[2], a4[3]);
#pragma unroll
                    for (int i = 0; i < 4; i++) a4[i] = 0.f;
                }
            }
        }
    }

    // --- rowmax reduce ---
#pragma unroll
    for (int mb = 0; mb < 4; mb++)
#pragma unroll
        for (int h = 0; h < 2; h++) {
            float v = rmx[mb][h];
            v = fmaxf(v, __shfl_xor_sync(0xffffffffu, v, 1));
            v = fmaxf(v, __shfl_xor_sync(0xffffffffu, v, 2));
            rmx[mb][h] = v;
        }
    if ((lane & 3) == 0) {
#pragma unroll
        for (int mb = 0; mb < 4; mb++)
#pragma unroll
            for (int h = 0; h < 2; h++)
                rms[nw][mw * 64 + mb * 16 + (lane >> 2) + h * 8] = rmx[mb][h];
    }
    __syncthreads();
    if (t < 128) {
        float v = fmaxf(fmaxf(rms[0][t], rms[1][t]), fmaxf(rms[2][t], rms[3][t]));
        g_rowmax[b * HW + q0 + t] = v;
    }
}

// ============================================================
// Kernel 4 (attnBC): sparse softmax + V gather + FUSED epilogue.
//   grid (128, B), 1024 threads: one warp per q-row.
//   Phase 1: coalesced scan + gather -> M/S into smem.
//   Phase 2: coalesced c_x tiles -> out = S*IN(c_x)+M directly.
// ============================================================
__global__ __launch_bounds__(1024, 1) void attnBC_kernel(const float* __restrict__ c_x,
                                                         float* __restrict__ out) {
    extern __shared__ char dsm[];
    int*   keyL = (int*)dsm;                           // [32][CAP]
    float* pL   = (float*)(dsm + 32768);               // [32][CAP]
    float* sM   = (float*)(dsm + 65536);               // [32][MS_STRIDE]
    float* sS   = sM + 32 * MS_STRIDE;                 // [32][MS_STRIDE]
    __shared__ int s_cnt[32];

    int b  = blockIdx.y;
    int q0 = blockIdx.x * 32;
    int t  = threadIdx.x, qr = t >> 5, lane = t & 31;
    int q  = q0 + qr;

    if (lane == 0) s_cnt[qr] = 0;
    __syncwarp();

    float m   = g_rowmax[b * HW + q];
    float thr = m - 34.0f;                       // 2^-34 ~ 6e-11
    const float4* Lr = (const float4*)(g_L + ((size_t)b * HW + q) * HW);
    const float*  Vg = g_Vt + (size_t)b * HW * CD;
    int*   myKey = keyL + qr * CAP;
    float* myP   = pL   + qr * CAP;

    // --- coalesced interleaved scan ---
    float psum = 0.f;
#pragma unroll 4
    for (int i = 0; i < 32; i++) {
        int k4 = i * 32 + lane;
        float4 l4 = Lr[k4];
        float mx = fmaxf(fmaxf(l4.x, l4.y), fmaxf(l4.z, l4.w));
        if (mx > thr) {
#pragma unroll
            for (int jj = 0; jj < 4; jj++) {
                float lv = (&l4.x)[jj];
                if (lv > thr) {
                    float p;
                    asm("ex2.approx.f32 %0, %1;" : "=f"(p) : "f"(lv - m));
                    psum += p;
                    int idx = atomicAdd(&s_cnt[qr], 1);
                    if (idx < CAP) { myKey[idx] = k4 * 4 + jj; myP[idx] = p; }
                }
            }
        }
    }
#pragma unroll
    for (int o = 16; o; o >>= 1)
        psum += __shfl_xor_sync(0xffffffffu, psum, o);
    __syncwarp();

    // --- cooperative gather: thread covers 16 v-elements ---
    int n = min(s_cnt[qr], CAP);
    float accM[16], accM2[16];
#pragma unroll
    for (int i = 0; i < 16; i++) { accM[i] = 0.f; accM2[i] = 0.f; }

    for (int i = 0; i < n; i++) {
        int   k = myKey[i];
        float p = myP[i];
        const float4* vr = (const float4*)(Vg + (size_t)k * CD) + lane;
#pragma unroll
        for (int j = 0; j < 4; j++) {
            float4 v = vr[j << 5];
            float a0 = p * v.x, a1 = p * v.y, a2 = p * v.z, a3 = p * v.w;
            accM[4*j]   += a0; accM2[4*j]   = fmaf(a0, v.x, accM2[4*j]);
            accM[4*j+1] += a1; accM2[4*j+1] = fmaf(a1, v.y, accM2[4*j+1]);
            accM[4*j+2] += a2; accM2[4*j+2] = fmaf(a2, v.z, accM2[4*j+2]);
            accM[4*j+3] += a3; accM2[4*j+3] = fmaf(a3, v.w, accM2[4*j+3]);
        }
    }

    // --- finalize into smem M/S ---
    float inv = 1.f / psum;
#pragma unroll
    for (int j = 0; j < 4; j++) {
        float4 mv, sv;
        float mm, e2, var;
        mm = accM[4*j] * inv;   e2 = accM2[4*j] * inv;   var = e2 - mm * mm;
        mv.x = mm; sv.x = sqrtf(fmaxf(var, 1e-6f));
        mm = accM[4*j+1] * inv; e2 = accM2[4*j+1] * inv; var = e2 - mm * mm;
        mv.y = mm; sv.y = sqrtf(fmaxf(var, 1e-6f));
        mm = accM[4*j+2] * inv; e2 = accM2[4*j+2] * inv; var = e2 - mm * mm;
        mv.z = mm; sv.z = sqrtf(fmaxf(var, 1e-6f));
        mm = accM[4*j+3] * inv; e2 = accM2[4*j+3] * inv; var = e2 - mm * mm;
        mv.w = mm; sv.w = sqrtf(fmaxf(var, 1e-6f));
        int v = j * 128 + lane * 4;
        *(float4*)(sM + qr * MS_STRIDE + v) = mv;
        *(float4*)(sS + qr * MS_STRIDE + v) = sv;
    }
    __syncthreads();

    // --- phase 2: fused epilogue ---
    // thread (qr=ty -> v offset, lane=tx -> q offset); 16 v-tiles of 32
    int ty = qr, tx = lane;
#pragma unroll 2
    for (int v0 = 0; v0 < CD; v0 += 32) {
        int v = v0 + ty;
        float mean = g_mean[2 * B * CD + b * CD + v];
        float rstd = g_rstd[2 * B * CD + b * CD + v];
        size_t off = ((size_t)b * CD + v) * HW + q0 + tx;
        float cn = (c_x[off] - mean) * rstd;
        out[off] = sS[tx * MS_STRIDE + v] * cn + sM[tx * MS_STRIDE + v];
    }
}

// ============================================================
extern "C" void kernel_launch(void* const* d_in, const int* in_sizes, int n_in,
                              void* d_out, int out_size) {
    const float* c_x  = (const float*)d_in[0];
    const float* s_x  = (const float*)d_in[1];
    const float* c_1x = (const float*)d_in[2];
    const float* s_1x = (const float*)d_in[3];
    float* out = (float*)d_out;

    stats_kernel<<<dim3(B * CD, 3), 256>>>(c_x, c_1x, s_1x);
    prep_kernel<<<dim3(HW / 32, CD / 32, 12), dim3(32, 8)>>>(c_1x, s_1x, s_x);

    cudaFuncSetAttribute(attnA_kernel, cudaFuncAttributeMaxDynamicSharedMemorySize, SMEM_DYN);
    attnA_kernel<<<dim3(HW / ATQ, B), 256, SMEM_DYN>>>();

    cudaFuncSetAttribute(attnBC_kernel, cudaFuncAttributeMaxDynamicSharedMemorySize, BC_SMEM);
    attnBC_kernel<<<dim3(HW / 32, B), 1024, BC_SMEM>>>(c_x, out);
}